// round 15
// baseline (speedup 1.0000x reference)
#include <cuda_runtime.h>
#include <cuda_fp16.h>
#include <cstdint>

#define M_TOK 128
#define HID   4096
#define INTER 11008
#define BN    64
#define BK    32
#define NT    128
#define KS1   4            // max GEMM1 planes (4-split tiles)
#define KS2   7            // GEMM2 K-split -> grid 448 ~= 1 wave of 444 slots

// GEMM1 flattened grid: 300 tiles x 4 splits + 44 tiles x 3 splits = 1332 = 3*444
#define G1_FOUR_TILES 300
#define G1_FOUR_CTAS  1200

#define RS        80                    // fp16 A-tile row stride (64B data + 16B pad)
#define RING_A_B  (128 * RS)            // 10240: A fp16 stage (128 rows)
#define RING_W_B  (BN * 128)            // 8192:  W fp32 stage (64 rows, swizzled)
#define STAGE_B   (RING_A_B + RING_W_B) // 18432
#define NSTAGE    4
#define SMEM_BYTES (NSTAGE * STAGE_B)   // 73728 -> 3 CTAs/SM

// ---------------- scratch (device globals; no allocation allowed) ----------------
__device__ __align__(16) __half g_xh[M_TOK * HID];
__device__ __align__(16) __half g_up_h  [KS1 * M_TOK * INTER];   // fp16 partials
__device__ __align__(16) __half g_gate_h[KS1 * M_TOK * INTER];   // fp16 partials
__device__ __align__(16) __half g_h [M_TOK * INTER];
__device__ __align__(16) float  g_p2[KS2 * M_TOK * HID];         // fp32 partials

// ---------------- helpers ----------------
__device__ __forceinline__ uint32_t smem_u32(const void* p) {
    uint32_t r;
    asm("{ .reg .u64 t; cvta.to.shared.u64 t, %1; cvt.u32.u64 %0, t; }" : "=r"(r) : "l"(p));
    return r;
}

#define CP16(dst, src) \
    asm volatile("cp.async.cg.shared.global [%0], [%1], 16;" :: "r"(dst), "l"(src))
#define CP_COMMIT() asm volatile("cp.async.commit_group;")
#define CP_WAIT2()  asm volatile("cp.async.wait_group 2;")

#define LDSM4(r, a)                                                          \
    asm volatile("ldmatrix.sync.aligned.m8n8.x4.shared.b16 {%0,%1,%2,%3}, [%4];" \
        : "=r"((r)[0]), "=r"((r)[1]), "=r"((r)[2]), "=r"((r)[3]) : "r"(a))

#define MMA16816(c, a, b0, b1)                                               \
    asm volatile("mma.sync.aligned.m16n8k16.row.col.f32.f16.f16.f32 "        \
        "{%0,%1,%2,%3}, {%4,%5,%6,%7}, {%8,%9}, {%0,%1,%2,%3};"              \
        : "+f"((c)[0]), "+f"((c)[1]), "+f"((c)[2]), "+f"((c)[3])             \
        : "r"((a)[0]), "r"((a)[1]), "r"((a)[2]), "r"((a)[3]),                \
          "r"(b0), "r"(b1))

__device__ __forceinline__ uint32_t cvt_h2(float2 f) {
    __half2 h = __float22half2_rn(f);
    return *reinterpret_cast<uint32_t*>(&h);
}

// issue one pipeline stage: A fp16 (4 x 16B/thread) + W fp32 swizzled (4 x 16B/thread)
__device__ __forceinline__ void issue_stage(
    uint32_t sbase, int slot, const __half* __restrict__ A, int lda,
    const float* __restrict__ W, int Ktot, int n0, int kb, int tid)
{
    const uint32_t dA = sbase + slot * STAGE_B;
    const uint32_t dW = dA + RING_A_B;
    #pragma unroll
    for (int i = 0; i < 4; ++i) {
        const int c = tid + i * NT;          // 512 chunks: row = c>>2, col16 = c&3
        const int row = c >> 2, col = c & 3;
        CP16(dA + row * RS + col * 16, A + (size_t)row * lda + kb + col * 8);
    }
    #pragma unroll
    for (int i = 0; i < 4; ++i) {
        const int c = tid + i * NT;          // 512 chunks: row = c>>3 (0..63), col = c&7
        const int row = c >> 3, col = c & 7;
        const uint32_t off = (uint32_t)(row * 128 + ((col * 16) ^ ((row & 3) * 32)));
        CP16(dW + off, W + (size_t)(n0 + row) * Ktot + kb + col * 4);
    }
}

// ============================================================================
// 128x64-tile fp16 HMMA GEMM, 4-slot cp.async ring, B-frags direct from fp32.
// 128 threads, 4 warps 2(M)x2(N), warp tile 64x32.
// FLAT=true  (GEMM1): 1D grid 1332; tiles 0..299 -> 4 splits klen 1024,
//                     tiles 300..343 -> 3 splits klen 1376/1376/1344.
//                     fp16 partial planes.
// FLAT=false (GEMM2): 2D grid (ntiles, KS2), klen_base/extra; fp32 planes.
// ============================================================================
template <bool FLAT>
__global__ __launch_bounds__(NT, 3)
void gemm_f16(const float* __restrict__ Wa, void* __restrict__ outa,
              const float* __restrict__ Wb, void* __restrict__ outb,
              int nsplit, int Ntot, int Ktot, int klen_base, int extra,
              const __half* __restrict__ A, int lda)
{
    extern __shared__ __align__(16) char smem[];
    const uint32_t sbase = smem_u32(smem);

    const int tid = threadIdx.x;
    const int l   = tid & 31;
    const int w   = tid >> 5;
    const int wr  = w >> 1;      // 0..1 (64 M-rows)
    const int wc  = w & 1;       // 0..1 (32 N-cols)

    const float* W; void* outv; int n0, k0, klen; size_t plane;
    if (FLAT) {
        const int id = blockIdx.x;
        int t, s;
        if (id < G1_FOUR_CTAS) {
            t = id >> 2; s = id & 3;
            k0 = s * 1024; klen = 1024;
        } else {
            const int r = id - G1_FOUR_CTAS;
            const int q = r / 3;
            t = G1_FOUR_TILES + q; s = r - q * 3;
            k0 = s * 1376; klen = (s == 2) ? 1344 : 1376;
        }
        if (t < nsplit) { W = Wa; outv = outa; n0 = t * BN; }
        else            { W = Wb; outv = outb; n0 = (t - nsplit) * BN; }
        plane = (size_t)s * M_TOK * Ntot;
    } else {
        if ((int)blockIdx.x < nsplit) { W = Wa; outv = outa; n0 = blockIdx.x * BN; }
        else                          { W = Wb; outv = outb; n0 = (blockIdx.x - nsplit) * BN; }
        const int y = blockIdx.y;
        k0 = y * klen_base + (y < extra ? y : extra) * 32;
        klen = klen_base + (y < extra ? 32 : 0);
        plane = (size_t)y * M_TOK * Ntot;
    }

    // A ldmatrix per-lane offsets (4 x 16-row fragments per warp)
    const int lrow = l & 15;
    const int lkB  = (l >> 4) * 16;
    uint32_t aoff[4];
    #pragma unroll
    for (int i = 0; i < 4; ++i)
        aoff[i] = (uint32_t)((wr * 64 + i * 16 + lrow) * RS + lkB);

    // B-fragment per-lane constants (fp32 LDS.64 path)
    const int nl = l >> 2;
    const int q8 = (l & 3) * 8;
    const uint32_t sw = (uint32_t)((nl & 3) * 32);

    float c[4][4][4];
    #pragma unroll
    for (int i = 0; i < 4; ++i)
        #pragma unroll
        for (int j = 0; j < 4; ++j)
            #pragma unroll
            for (int t = 0; t < 4; ++t) c[i][j][t] = 0.f;

    const int S = klen / BK;

    // prologue: 3 stages in flight
    #pragma unroll
    for (int p = 0; p < NSTAGE - 1; ++p) {
        issue_stage(sbase, p, A, lda, W, Ktot, n0, k0 + p * BK, tid);
        CP_COMMIT();
    }

    for (int s = 0; s < S; ++s) {
        const int slot = s & (NSTAGE - 1);
        const uint32_t sA = sbase + slot * STAGE_B;
        const char* wB = smem + slot * STAGE_B + RING_A_B;

        CP_WAIT2();             // group s complete
        __syncthreads();        // refill slot is free (consumed at s-1)

        if (s + NSTAGE - 1 < S)
            issue_stage(sbase, (s + NSTAGE - 1) & (NSTAGE - 1),
                        A, lda, W, Ktot, n0, k0 + (s + NSTAGE - 1) * BK, tid);
        CP_COMMIT();

        // ---- MMA on stage s: A via ldmatrix, B via LDS.64 + cvt ----
        #pragma unroll
        for (int kk = 0; kk < 2; ++kk) {
            uint32_t afr[4][4];
            #pragma unroll
            for (int i = 0; i < 4; ++i) LDSM4(afr[i], sA + aoff[i] + kk * 32);

            const uint32_t o0 = ((uint32_t)(kk * 64 + q8)) ^ sw;
            const uint32_t o1 = o0 ^ 32u;
            #pragma unroll
            for (int j2 = 0; j2 < 2; ++j2) {
                const char* r0p = wB + (wc * 32 + j2 * 16 + nl) * 128;
                const char* r1p = r0p + 8 * 128;
                const float2 f00 = *reinterpret_cast<const float2*>(r0p + o0);
                const float2 f01 = *reinterpret_cast<const float2*>(r0p + o1);
                const float2 f10 = *reinterpret_cast<const float2*>(r1p + o0);
                const float2 f11 = *reinterpret_cast<const float2*>(r1p + o1);
                const uint32_t b00 = cvt_h2(f00), b01 = cvt_h2(f01);
                const uint32_t b10 = cvt_h2(f10), b11 = cvt_h2(f11);
                #pragma unroll
                for (int i = 0; i < 4; ++i) {
                    MMA16816(c[i][j2 * 2 + 0], afr[i], b00, b01);
                    MMA16816(c[i][j2 * 2 + 1], afr[i], b10, b11);
                }
            }
        }
    }

    // ---- epilogue: direct stores of C fragments (fp16 or fp32 partials) ----
    const int g = l >> 2, q = l & 3;
    #pragma unroll
    for (int i = 0; i < 4; ++i) {
        const int row = wr * 64 + i * 16 + g;
        #pragma unroll
        for (int j = 0; j < 4; ++j) {
            const int col = n0 + wc * 32 + j * 8 + q * 2;
            if (FLAT) {
                __half* out = (__half*)outv + plane;
                *reinterpret_cast<uint32_t*>(out + (size_t)row * Ntot + col) =
                    cvt_h2(make_float2(c[i][j][0], c[i][j][1]));
                *reinterpret_cast<uint32_t*>(out + (size_t)(row + 8) * Ntot + col) =
                    cvt_h2(make_float2(c[i][j][2], c[i][j][3]));
            } else {
                float* out = (float*)outv + plane;
                *reinterpret_cast<float2*>(out + (size_t)row * Ntot + col) =
                    make_float2(c[i][j][0], c[i][j][1]);
                *reinterpret_cast<float2*>(out + (size_t)(row + 8) * Ntot + col) =
                    make_float2(c[i][j][2], c[i][j][3]);
            }
        }
    }
}

// ============================================================================
// Elementwise kernels
// ============================================================================
__global__ void convert_x_kernel(const float* __restrict__ x) {
    const int i = (blockIdx.x * blockDim.x + threadIdx.x) * 4;
    const float4 v = *reinterpret_cast<const float4*>(x + i);
    uint2 o;
    o.x = cvt_h2(make_float2(v.x, v.y));
    o.y = cvt_h2(make_float2(v.z, v.w));
    *reinterpret_cast<uint2*>(g_xh + i) = o;
}

__device__ __forceinline__ float silu_mul(float u, float g) {
    return (u / (1.0f + expf(-u))) * g;
}

// sums fp16 K-split planes (up: 4; gate: 4 if n<8192 else 3), scales, SwiGLU
__global__ void swiglu_kernel(const float* __restrict__ w1s,
                              const float* __restrict__ w3s) {
    const int i = (blockIdx.x * blockDim.x + threadIdx.x) * 4;
    const int MI = M_TOK * INTER;
    const int n = i % INTER;
    float2 u01 = make_float2(0.f, 0.f), u23 = make_float2(0.f, 0.f);
    float2 t01 = make_float2(0.f, 0.f), t23 = make_float2(0.f, 0.f);
    #pragma unroll
    for (int p = 0; p < 3; ++p) {
        const uint2 av = *reinterpret_cast<const uint2*>(g_up_h + i + p * MI);
        const uint2 bv = *reinterpret_cast<const uint2*>(g_gate_h + i + p * MI);
        const float2 a01 = __half22float2(*reinterpret_cast<const __half2*>(&av.x));
        const float2 a23 = __half22float2(*reinterpret_cast<const __half2*>(&av.y));
        const float2 b01 = __half22float2(*reinterpret_cast<const __half2*>(&bv.x));
        const float2 b23 = __half22float2(*reinterpret_cast<const __half2*>(&bv.y));
        u01.x += a01.x; u01.y += a01.y; u23.x += a23.x; u23.y += a23.y;
        t01.x += b01.x; t01.y += b01.y; t23.x += b23.x; t23.y += b23.y;
    }
    {   // plane 3: up always; gate only for n < 8192 (4-split region)
        const uint2 av = *reinterpret_cast<const uint2*>(g_up_h + i + 3 * MI);
        const float2 a01 = __half22float2(*reinterpret_cast<const __half2*>(&av.x));
        const float2 a23 = __half22float2(*reinterpret_cast<const __half2*>(&av.y));
        u01.x += a01.x; u01.y += a01.y; u23.x += a23.x; u23.y += a23.y;
        if (n < 8192) {
            const uint2 bv = *reinterpret_cast<const uint2*>(g_gate_h + i + 3 * MI);
            const float2 b01 = __half22float2(*reinterpret_cast<const __half2*>(&bv.x));
            const float2 b23 = __half22float2(*reinterpret_cast<const __half2*>(&bv.y));
            t01.x += b01.x; t01.y += b01.y; t23.x += b23.x; t23.y += b23.y;
        }
    }
    const float4 s1 = *reinterpret_cast<const float4*>(w1s + n);
    const float4 s3 = *reinterpret_cast<const float4*>(w3s + n);
    float r0 = silu_mul(u01.x * s1.x, t01.x * s3.x);
    float r1 = silu_mul(u01.y * s1.y, t01.y * s3.y);
    float r2 = silu_mul(u23.x * s1.z, t23.x * s3.z);
    float r3 = silu_mul(u23.y * s1.w, t23.y * s3.w);
    uint2 o;
    o.x = cvt_h2(make_float2(r0, r1));
    o.y = cvt_h2(make_float2(r2, r3));
    *reinterpret_cast<uint2*>(g_h + i) = o;
}

__global__ void reduce_kernel(float* __restrict__ out, const float* __restrict__ w2s) {
    const int i = (blockIdx.x * blockDim.x + threadIdx.x) * 4;
    const int MH = M_TOK * HID;
    float4 s = make_float4(0.f, 0.f, 0.f, 0.f);
    #pragma unroll
    for (int p = 0; p < KS2; ++p) {
        const float4 v = *reinterpret_cast<const float4*>(g_p2 + i + p * MH);
        s.x += v.x; s.y += v.y; s.z += v.z; s.w += v.w;
    }
    const float4 sc = *reinterpret_cast<const float4*>(w2s + (i & (HID - 1)));
    *reinterpret_cast<float4*>(out + i) =
        make_float4(s.x * sc.x, s.y * sc.y, s.z * sc.z, s.w * sc.w);
}

// ============================================================================
// Launch
// ============================================================================
extern "C" void kernel_launch(void* const* d_in, const int* in_sizes, int n_in,
                              void* d_out, int out_size) {
    const float* x   = (const float*)d_in[0];
    const float* w1  = (const float*)d_in[1];
    const float* w1s = (const float*)d_in[2];
    const float* w3  = (const float*)d_in[3];
    const float* w3s = (const float*)d_in[4];
    const float* w2  = (const float*)d_in[5];
    const float* w2s = (const float*)d_in[6];
    float* out = (float*)d_out;

    cudaFuncSetAttribute(gemm_f16<true>,
                         cudaFuncAttributeMaxDynamicSharedMemorySize, SMEM_BYTES);
    cudaFuncSetAttribute(gemm_f16<false>,
                         cudaFuncAttributeMaxDynamicSharedMemorySize, SMEM_BYTES);

    void *xh, *up, *gate, *h, *p2;
    cudaGetSymbolAddress(&xh, g_xh);
    cudaGetSymbolAddress(&up, g_up_h);
    cudaGetSymbolAddress(&gate, g_gate_h);
    cudaGetSymbolAddress(&h, g_h);
    cudaGetSymbolAddress(&p2, g_p2);

    // 1. x -> fp16
    convert_x_kernel<<<(M_TOK * HID) / (4 * 256), 256>>>(x);

    // 2. GEMM1: up (w1) + gate (w3), flattened grid 1332 = 3 * 444 slots
    gemm_f16<true><<<1332, NT, SMEM_BYTES>>>(
        w1, up, w3, gate,
        INTER / BN, INTER, HID, 0, 0,
        (const __half*)xh, HID);

    // 3. SwiGLU (sums fp16 K-split planes, applies scales) -> fp16 h
    swiglu_kernel<<<(M_TOK * INTER) / (4 * 256), 256>>>(w1s, w3s);

    // 4. GEMM2: fp32 partials, grid (64, 7) = 448 CTAs ~= 1 wave
    //    klen chunks: 344 = 7*49 + 1 -> base 49*32 = 1568, extra = 1 (+32)
    gemm_f16<false><<<dim3(HID / BN, KS2), NT, SMEM_BYTES>>>(
        w2, p2, w2, p2,
        HID / BN, HID, INTER, 1568, 1,
        (const __half*)h, INTER);

    // 5. reduce K-split planes + w2_s scale
    reduce_kernel<<<(M_TOK * HID) / (4 * 256), 256>>>(out, w2s);
}

// round 16
// speedup vs baseline: 1.4671x; 1.4671x over previous
#include <cuda_runtime.h>
#include <cuda_fp16.h>
#include <cstdint>

#define M_TOK 128
#define HID   4096
#define INTER 11008
#define BN    64
#define BK    32
#define NT    128
#define KS1   4            // GEMM1 K-split (klen 1024, 32 stages)
#define KS2   7            // GEMM2 K-split -> grid 448 ~= 1 wave of 444 slots

#define RS        80                    // fp16 A-tile row stride (64B data + 16B pad)
#define RING_A_B  (128 * RS)            // 10240: A fp16 stage (128 rows)
#define RING_W_B  (BN * 128)            // 8192:  W fp32 stage (64 rows, swizzled)
#define STAGE_B   (RING_A_B + RING_W_B) // 18432
#define NSTAGE    4
#define SMEM_BYTES (NSTAGE * STAGE_B)   // 73728 -> 3 CTAs/SM

// ---------------- scratch (device globals; no allocation allowed) ----------------
__device__ __align__(16) __half g_xh[M_TOK * HID];
__device__ __align__(16) __half g_up_h  [KS1 * M_TOK * INTER];   // fp16 partials
__device__ __align__(16) __half g_gate_h[KS1 * M_TOK * INTER];   // fp16 partials
__device__ __align__(16) __half g_h [M_TOK * INTER];
__device__ __align__(16) float  g_p2[KS2 * M_TOK * HID];         // fp32 partials

// ---------------- helpers ----------------
__device__ __forceinline__ uint32_t smem_u32(const void* p) {
    uint32_t r;
    asm("{ .reg .u64 t; cvta.to.shared.u64 t, %1; cvt.u32.u64 %0, t; }" : "=r"(r) : "l"(p));
    return r;
}

#define CP16(dst, src) \
    asm volatile("cp.async.cg.shared.global [%0], [%1], 16;" :: "r"(dst), "l"(src))
#define CP_COMMIT() asm volatile("cp.async.commit_group;")
#define CP_WAIT2()  asm volatile("cp.async.wait_group 2;")

#define LDSM4(r, a)                                                          \
    asm volatile("ldmatrix.sync.aligned.m8n8.x4.shared.b16 {%0,%1,%2,%3}, [%4];" \
        : "=r"((r)[0]), "=r"((r)[1]), "=r"((r)[2]), "=r"((r)[3]) : "r"(a))

#define MMA16816(c, a, b0, b1)                                               \
    asm volatile("mma.sync.aligned.m16n8k16.row.col.f32.f16.f16.f32 "        \
        "{%0,%1,%2,%3}, {%4,%5,%6,%7}, {%8,%9}, {%0,%1,%2,%3};"              \
        : "+f"((c)[0]), "+f"((c)[1]), "+f"((c)[2]), "+f"((c)[3])             \
        : "r"((a)[0]), "r"((a)[1]), "r"((a)[2]), "r"((a)[3]),                \
          "r"(b0), "r"(b1))

__device__ __forceinline__ uint32_t cvt_h2(float2 f) {
    __half2 h = __float22half2_rn(f);
    return *reinterpret_cast<uint32_t*>(&h);
}

// issue one pipeline stage: A fp16 (4 x 16B/thread) + W fp32 swizzled (4 x 16B/thread)
__device__ __forceinline__ void issue_stage(
    uint32_t sbase, int slot, const __half* __restrict__ A, int lda,
    const float* __restrict__ W, int Ktot, int n0, int kb, int tid)
{
    const uint32_t dA = sbase + slot * STAGE_B;
    const uint32_t dW = dA + RING_A_B;
    #pragma unroll
    for (int i = 0; i < 4; ++i) {
        const int c = tid + i * NT;          // 512 chunks: row = c>>2, col16 = c&3
        const int row = c >> 2, col = c & 3;
        CP16(dA + row * RS + col * 16, A + (size_t)row * lda + kb + col * 8);
    }
    #pragma unroll
    for (int i = 0; i < 4; ++i) {
        const int c = tid + i * NT;          // 512 chunks: row = c>>3 (0..63), col = c&7
        const int row = c >> 3, col = c & 7;
        const uint32_t off = (uint32_t)(row * 128 + ((col * 16) ^ ((row & 3) * 32)));
        CP16(dW + off, W + (size_t)(n0 + row) * Ktot + kb + col * 4);
    }
}

// ============================================================================
// 128x64-tile fp16 HMMA GEMM, 4-slot cp.async ring, B-frags direct from fp32.
// 128 threads, 4 warps 2(M)x2(N), warp tile 64x32.  (R7/R13 mainloop.)
// HALF_OUT: partial planes stored fp16 (GEMM1) or fp32 (GEMM2).
// K-split: k0/klen from blockIdx.y, klen_base (+32 elems for y < extra).
// ============================================================================
template <bool HALF_OUT>
__global__ __launch_bounds__(NT, 3)
void gemm_f16(const float* __restrict__ Wa, void* __restrict__ outa,
              const float* __restrict__ Wb, void* __restrict__ outb,
              int nsplit, int Ntot, int Ktot, int klen_base, int extra,
              const __half* __restrict__ A, int lda)
{
    extern __shared__ __align__(16) char smem[];
    const uint32_t sbase = smem_u32(smem);

    const int tid = threadIdx.x;
    const int l   = tid & 31;
    const int w   = tid >> 5;
    const int wr  = w >> 1;      // 0..1 (64 M-rows)
    const int wc  = w & 1;       // 0..1 (32 N-cols)

    const float* W; void* outv; int n0;
    if ((int)blockIdx.x < nsplit) { W = Wa; outv = outa; n0 = blockIdx.x * BN; }
    else                          { W = Wb; outv = outb; n0 = (blockIdx.x - nsplit) * BN; }
    const int y = blockIdx.y;
    const int k0 = y * klen_base + (y < extra ? y : extra) * 32;
    const int klen = klen_base + (y < extra ? 32 : 0);
    const size_t plane = (size_t)y * M_TOK * Ntot;

    // A ldmatrix per-lane offsets (4 x 16-row fragments per warp)
    const int lrow = l & 15;
    const int lkB  = (l >> 4) * 16;
    uint32_t aoff[4];
    #pragma unroll
    for (int i = 0; i < 4; ++i)
        aoff[i] = (uint32_t)((wr * 64 + i * 16 + lrow) * RS + lkB);

    // B-fragment per-lane constants (fp32 LDS.64 path)
    const int nl = l >> 2;
    const int q8 = (l & 3) * 8;
    const uint32_t sw = (uint32_t)((nl & 3) * 32);

    float c[4][4][4];
    #pragma unroll
    for (int i = 0; i < 4; ++i)
        #pragma unroll
        for (int j = 0; j < 4; ++j)
            #pragma unroll
            for (int t = 0; t < 4; ++t) c[i][j][t] = 0.f;

    const int S = klen / BK;

    // prologue: 3 stages in flight
    #pragma unroll
    for (int p = 0; p < NSTAGE - 1; ++p) {
        issue_stage(sbase, p, A, lda, W, Ktot, n0, k0 + p * BK, tid);
        CP_COMMIT();
    }

    for (int s = 0; s < S; ++s) {
        const int slot = s & (NSTAGE - 1);
        const uint32_t sA = sbase + slot * STAGE_B;
        const char* wB = smem + slot * STAGE_B + RING_A_B;

        CP_WAIT2();             // group s complete
        __syncthreads();        // refill slot is free (consumed at s-1)

        if (s + NSTAGE - 1 < S)
            issue_stage(sbase, (s + NSTAGE - 1) & (NSTAGE - 1),
                        A, lda, W, Ktot, n0, k0 + (s + NSTAGE - 1) * BK, tid);
        CP_COMMIT();

        // ---- MMA on stage s: A via ldmatrix, B via LDS.64 + cvt ----
        #pragma unroll
        for (int kk = 0; kk < 2; ++kk) {
            uint32_t afr[4][4];
            #pragma unroll
            for (int i = 0; i < 4; ++i) LDSM4(afr[i], sA + aoff[i] + kk * 32);

            const uint32_t o0 = ((uint32_t)(kk * 64 + q8)) ^ sw;
            const uint32_t o1 = o0 ^ 32u;
            #pragma unroll
            for (int j2 = 0; j2 < 2; ++j2) {
                const char* r0p = wB + (wc * 32 + j2 * 16 + nl) * 128;
                const char* r1p = r0p + 8 * 128;
                const float2 f00 = *reinterpret_cast<const float2*>(r0p + o0);
                const float2 f01 = *reinterpret_cast<const float2*>(r0p + o1);
                const float2 f10 = *reinterpret_cast<const float2*>(r1p + o0);
                const float2 f11 = *reinterpret_cast<const float2*>(r1p + o1);
                const uint32_t b00 = cvt_h2(f00), b01 = cvt_h2(f01);
                const uint32_t b10 = cvt_h2(f10), b11 = cvt_h2(f11);
                #pragma unroll
                for (int i = 0; i < 4; ++i) {
                    MMA16816(c[i][j2 * 2 + 0], afr[i], b00, b01);
                    MMA16816(c[i][j2 * 2 + 1], afr[i], b10, b11);
                }
            }
        }
    }

    // ---- epilogue: direct stores of C fragments (fp16 or fp32 partials) ----
    const int g = l >> 2, q = l & 3;
    #pragma unroll
    for (int i = 0; i < 4; ++i) {
        const int row = wr * 64 + i * 16 + g;
        #pragma unroll
        for (int j = 0; j < 4; ++j) {
            const int col = n0 + wc * 32 + j * 8 + q * 2;
            if (HALF_OUT) {
                __half* out = (__half*)outv + plane;
                *reinterpret_cast<uint32_t*>(out + (size_t)row * Ntot + col) =
                    cvt_h2(make_float2(c[i][j][0], c[i][j][1]));
                *reinterpret_cast<uint32_t*>(out + (size_t)(row + 8) * Ntot + col) =
                    cvt_h2(make_float2(c[i][j][2], c[i][j][3]));
            } else {
                float* out = (float*)outv + plane;
                *reinterpret_cast<float2*>(out + (size_t)row * Ntot + col) =
                    make_float2(c[i][j][0], c[i][j][1]);
                *reinterpret_cast<float2*>(out + (size_t)(row + 8) * Ntot + col) =
                    make_float2(c[i][j][2], c[i][j][3]);
            }
        }
    }
}

// ============================================================================
// Elementwise kernels
// ============================================================================
// 2 float4 per thread (MLP 2): 65536 threads cover M_TOK*HID floats
__global__ void convert_x_kernel(const float* __restrict__ x) {
    const int t = blockIdx.x * blockDim.x + threadIdx.x;
    const int i0 = t * 4;
    const int i1 = i0 + (M_TOK * HID / 2);
    const float4 v0 = *reinterpret_cast<const float4*>(x + i0);
    const float4 v1 = *reinterpret_cast<const float4*>(x + i1);
    uint2 o0, o1;
    o0.x = cvt_h2(make_float2(v0.x, v0.y));
    o0.y = cvt_h2(make_float2(v0.z, v0.w));
    o1.x = cvt_h2(make_float2(v1.x, v1.y));
    o1.y = cvt_h2(make_float2(v1.z, v1.w));
    *reinterpret_cast<uint2*>(g_xh + i0) = o0;
    *reinterpret_cast<uint2*>(g_xh + i1) = o1;
}

__device__ __forceinline__ float silu_mul(float u, float g) {
    return (u / (1.0f + expf(-u))) * g;
}

// sums fp16 K-split planes, applies per-channel scales, SwiGLU -> fp16 h
__global__ void swiglu_kernel(const float* __restrict__ w1s,
                              const float* __restrict__ w3s) {
    const int i = (blockIdx.x * blockDim.x + threadIdx.x) * 4;
    const int MI = M_TOK * INTER;
    const int n = i % INTER;
    float2 u01 = make_float2(0.f, 0.f), u23 = make_float2(0.f, 0.f);
    float2 t01 = make_float2(0.f, 0.f), t23 = make_float2(0.f, 0.f);
    #pragma unroll
    for (int p = 0; p < KS1; ++p) {
        const uint2 av = *reinterpret_cast<const uint2*>(g_up_h + i + p * MI);
        const uint2 bv = *reinterpret_cast<const uint2*>(g_gate_h + i + p * MI);
        const float2 a01 = __half22float2(*reinterpret_cast<const __half2*>(&av.x));
        const float2 a23 = __half22float2(*reinterpret_cast<const __half2*>(&av.y));
        const float2 b01 = __half22float2(*reinterpret_cast<const __half2*>(&bv.x));
        const float2 b23 = __half22float2(*reinterpret_cast<const __half2*>(&bv.y));
        u01.x += a01.x; u01.y += a01.y; u23.x += a23.x; u23.y += a23.y;
        t01.x += b01.x; t01.y += b01.y; t23.x += b23.x; t23.y += b23.y;
    }
    const float4 s1 = *reinterpret_cast<const float4*>(w1s + n);
    const float4 s3 = *reinterpret_cast<const float4*>(w3s + n);
    float r0 = silu_mul(u01.x * s1.x, t01.x * s3.x);
    float r1 = silu_mul(u01.y * s1.y, t01.y * s3.y);
    float r2 = silu_mul(u23.x * s1.z, t23.x * s3.z);
    float r3 = silu_mul(u23.y * s1.w, t23.y * s3.w);
    uint2 o;
    o.x = cvt_h2(make_float2(r0, r1));
    o.y = cvt_h2(make_float2(r2, r3));
    *reinterpret_cast<uint2*>(g_h + i) = o;
}

__global__ void reduce_kernel(float* __restrict__ out, const float* __restrict__ w2s) {
    const int i = (blockIdx.x * blockDim.x + threadIdx.x) * 4;
    const int MH = M_TOK * HID;
    float4 s = make_float4(0.f, 0.f, 0.f, 0.f);
    #pragma unroll
    for (int p = 0; p < KS2; ++p) {
        const float4 v = *reinterpret_cast<const float4*>(g_p2 + i + p * MH);
        s.x += v.x; s.y += v.y; s.z += v.z; s.w += v.w;
    }
    const float4 sc = *reinterpret_cast<const float4*>(w2s + (i & (HID - 1)));
    *reinterpret_cast<float4*>(out + i) =
        make_float4(s.x * sc.x, s.y * sc.y, s.z * sc.z, s.w * sc.w);
}

// ============================================================================
// Launch
// ============================================================================
extern "C" void kernel_launch(void* const* d_in, const int* in_sizes, int n_in,
                              void* d_out, int out_size) {
    const float* x   = (const float*)d_in[0];
    const float* w1  = (const float*)d_in[1];
    const float* w1s = (const float*)d_in[2];
    const float* w3  = (const float*)d_in[3];
    const float* w3s = (const float*)d_in[4];
    const float* w2  = (const float*)d_in[5];
    const float* w2s = (const float*)d_in[6];
    float* out = (float*)d_out;

    cudaFuncSetAttribute(gemm_f16<true>,
                         cudaFuncAttributeMaxDynamicSharedMemorySize, SMEM_BYTES);
    cudaFuncSetAttribute(gemm_f16<false>,
                         cudaFuncAttributeMaxDynamicSharedMemorySize, SMEM_BYTES);

    void *xh, *up, *gate, *h, *p2;
    cudaGetSymbolAddress(&xh, g_xh);
    cudaGetSymbolAddress(&up, g_up_h);
    cudaGetSymbolAddress(&gate, g_gate_h);
    cudaGetSymbolAddress(&h, g_h);
    cudaGetSymbolAddress(&p2, g_p2);

    // 1. x -> fp16 (MLP-2: 65536 threads, 2 float4 each)
    convert_x_kernel<<<(M_TOK * HID) / (8 * 256), 256>>>(x);

    // 2. GEMM1: up (w1) + gate (w3), fp16 partials: grid (344, 4) = 1376 CTAs
    //    klen = 4096/4 = 1024 (extra = 0)
    gemm_f16<true><<<dim3(2 * (INTER / BN), KS1), NT, SMEM_BYTES>>>(
        w1, up, w3, gate,
        INTER / BN, INTER, HID, HID / KS1, 0,
        (const __half*)xh, HID);

    // 3. SwiGLU (sums fp16 K-split planes, applies scales) -> fp16 h
    swiglu_kernel<<<(M_TOK * INTER) / (4 * 256), 256>>>(w1s, w3s);

    // 4. GEMM2: fp32 partials, grid (64, 7) = 448 CTAs ~= 1 wave
    //    klen chunks: 344 = 7*49 + 1 -> base 49*32 = 1568, extra = 1 (+32)
    gemm_f16<false><<<dim3(HID / BN, KS2), NT, SMEM_BYTES>>>(
        w2, p2, w2, p2,
        HID / BN, HID, INTER, 1568, 1,
        (const __half*)h, INTER);

    // 5. reduce K-split planes + w2_s scale
    reduce_kernel<<<(M_TOK * HID) / (4 * 256), 256>>>(out, w2s);
}